// round 13
// baseline (speedup 1.0000x reference)
#include <cuda_runtime.h>
#include <cstdint>

// Foveated tokenizer: 5-level box-average pyramid over (3,4096,4096) int32 image.
// Token boxes exactly partition the image -> each pixel read exactly once.
// ~201 MB read + 3 MB write (float32 out), pure DRAM stream.
// R13: R7 job decomposition (proven best) + persistent CTAs with STATIC strided
//      job assignment: one launch, no atomics, no wave transitions, each CTA
//      runs ~6 jobs back-to-back separated only by a bar.sync.

#define IMG_DIM 4096
#define IMG_CH_STRIDE (IMG_DIM * IMG_DIM)

// Job layout (heavy levels first; identical to R7):
//   level 4 (s=16): 192 tok * 3 ch * 8 chunks = 4608 jobs   [0, 4608)
//   level 3 (s= 8): 192 tok * 3 ch * 2 chunks = 1152 jobs   [4608, 5760)
//   level 2 (s= 4): 192 tok * 3 ch * 1 chunk  =  576 jobs   [5760, 6336)
//   level 1 (s= 2): 192 tok * 3 ch * 1 chunk  =  576 jobs   [6336, 6912)
//   level 0 (s= 1): 256 tok * 3 ch * 1 chunk  =  768 jobs   [6912, 7680)
#define N_JOBS 7680
#define N_CTAS 1184   // 148 SMs * 8 resident CTAs -> all wave-1 resident

template <int LEVEL>
__device__ __forceinline__ void process_level(int job,
                                              const int* __restrict__ img,
                                              float* __restrict__ out,
                                              int* psum) {
    constexpr int S    = 1 << LEVEL;           // box stride in pixels
    constexpr int CHK  = (LEVEL == 4) ? 8 : (LEVEL == 3) ? 2 : 1; // chunks/(tok,ch)
    constexpr int NR   = 16 / CHK;             // output rows per chunk
    constexpr int W    = 16 * S;               // region width in pixels
    constexpr int VC   = W / 4;                // int4 columns
    constexpr int ROWS = NR * S;               // image rows per chunk
    constexpr int ITEMS = ROWS * VC;           // (row, vcol) load items
    constexpr int RPT  = (ITEMS >= 1024) ? ITEMS / 256 : 1;  // rows per thread
    constexpr int NACT = ITEMS / RPT;          // active threads in phase 1
    constexpr int NGE  = (S >= RPT) ? S / RPT : 1;  // row-groups per out-row
    constexpr int TOKBASE =
        (LEVEL == 0) ? 0 : (LEVEL == 1) ? 256 : (LEVEL == 2) ? 448
                                            : (LEVEL == 3) ? 640 : 832;
    constexpr int PER_TOK = 3 * CHK;
    constexpr int CORNER  = 2048 - 128 * S;    // pixel offset of level's grid (16-aligned)

    const int tl    = job / PER_TOK;           // token index within level
    const int rem   = job - tl * PER_TOK;
    const int ch    = rem / CHK;
    const int chunk = rem - ch * CHK;

    // Map level-local token index -> (row, col) on the 16x16 coarse grid.
    int row, col;
    if (LEVEL == 0) {
        row = tl >> 4; col = tl & 15;
    } else {
        // ring = 4 at every level >= 1
        if (tl < 64)       { row = tl >> 4;             col = tl & 15; }
        else if (tl < 128) { int k = tl - 64; row = 4 + (k >> 3);
                             int r = k & 7;             col = (r < 4) ? r : (r + 8); }
        else               { int k = tl - 128; row = 12 + (k >> 4); col = k & 15; }
    }

    const int cx  = CORNER + W * col;          // region top-left pixel (16B aligned)
    const int cy  = CORNER + W * row;
    const int oy0 = chunk * NR;                // first output row of this chunk
    const int ry0 = cy + S * oy0;              // first image row of this chunk

    const int* base = img + (size_t)ch * IMG_CH_STRIDE;
    const int tid = threadIdx.x;

    // Phase 1: every active thread owns one int4 column slice of RPT rows.
    // Fully unrolled -> RPT front-batched LDG.128.
    if (tid < NACT) {
        const int vcol = tid & (VC - 1);
        const int g    = tid / VC;             // row-group index
        const int4* p  = (const int4*)(base + (size_t)(ry0 + g * RPT) * IMG_DIM + cx)
                         + vcol;
        int4 a = make_int4(0, 0, 0, 0);
#pragma unroll
        for (int r = 0; r < RPT; r++) {
            int4 t = __ldcs(p);
            p += IMG_DIM / 4;
            a.x += t.x; a.y += t.y; a.z += t.z; a.w += t.w;
        }
        ((int4*)psum)[g * VC + vcol] = a;      // conflict-free 16B STS
    }
    __syncthreads();

    // Phase 2: combine NGE row-group partials x S scalar columns per output box.
    constexpr int NOUT = NR * 16;
    const int n = TOKBASE + tl;
    for (int o = tid; o < NOUT; o += 256) {
        const int oy = o >> 4;
        const int bx = o & 15;
        int sum = 0;
#pragma unroll
        for (int gg = 0; gg < NGE; gg++) {
            const int* s = psum + (oy * NGE + gg) * W + (bx << LEVEL);
#pragma unroll
            for (int i = 0; i < S; i++) sum += s[i];
        }
        // Exact floor-div by S*S (sum >= 0); value fits in [0,255].
        out[(((size_t)n * 3 + ch) << 8) + ((size_t)(oy0 + oy) << 4) + bx] =
            (float)(sum >> (2 * LEVEL));
    }
}

__global__ void __launch_bounds__(256, 8)
foveator_kernel(const int* __restrict__ img, float* __restrict__ out) {
    __shared__ int psum[1024];                 // 4KB partials

    // Static strided persistent loop: CTA b handles jobs b, b+1184, ...
    for (int b = blockIdx.x; b < N_JOBS; b += N_CTAS) {
        if (b < 4608)      process_level<4>(b,         img, out, psum);
        else if (b < 5760) process_level<3>(b - 4608,  img, out, psum);
        else if (b < 6336) process_level<2>(b - 5760,  img, out, psum);
        else if (b < 6912) process_level<1>(b - 6336,  img, out, psum);
        else               process_level<0>(b - 6912,  img, out, psum);
        __syncthreads();                       // psum reuse guard between jobs
    }
}

extern "C" void kernel_launch(void* const* d_in, const int* in_sizes, int n_in,
                              void* d_out, int out_size) {
    const int* img = (const int*)d_in[0];
    float* out = (float*)d_out;
    foveator_kernel<<<N_CTAS, 256>>>(img, out);
}

// round 14
// speedup vs baseline: 1.0491x; 1.0491x over previous
#include <cuda_runtime.h>
#include <cstdint>

// Foveated tokenizer: 5-level box-average pyramid over (3,4096,4096) int32 image.
// Token boxes exactly partition the image -> each pixel read exactly once.
// ~201 MB read + 3 MB write (float32 out), pure DRAM stream.
// FINAL (= R7, proven 33.5us / 79.3% DRAM): 2-D (vec-col x row-group)
// decomposition -> ALL 256 threads issue LDG.128; classic launch, heavy
// levels first, tiny light-level jobs drain the tail. Persistent/merged/
// shuffle variants were all benchmarked and lost (R8-R13).

#define IMG_DIM 4096
#define IMG_CH_STRIDE (IMG_DIM * IMG_DIM)

// Job layout (heavy levels first for wave-1 scheduling):
//   level 4 (s=16): 192 tok * 3 ch * 8 chunks = 4608 jobs   [0, 4608)
//   level 3 (s= 8): 192 tok * 3 ch * 2 chunks = 1152 jobs   [4608, 5760)
//   level 2 (s= 4): 192 tok * 3 ch * 1 chunk  =  576 jobs   [5760, 6336)
//   level 1 (s= 2): 192 tok * 3 ch * 1 chunk  =  576 jobs   [6336, 6912)
//   level 0 (s= 1): 256 tok * 3 ch * 1 chunk  =  768 jobs   [6912, 7680)
#define N_JOBS 7680

template <int LEVEL>
__device__ __forceinline__ void process_level(int job,
                                              const int* __restrict__ img,
                                              float* __restrict__ out,
                                              int* psum) {
    constexpr int S    = 1 << LEVEL;           // box stride in pixels
    constexpr int CHK  = (LEVEL == 4) ? 8 : (LEVEL == 3) ? 2 : 1; // chunks/(tok,ch)
    constexpr int NR   = 16 / CHK;             // output rows per chunk
    constexpr int W    = 16 * S;               // region width in pixels
    constexpr int VC   = W / 4;                // int4 columns
    constexpr int ROWS = NR * S;               // image rows per chunk
    constexpr int ITEMS = ROWS * VC;           // (row, vcol) load items
    constexpr int RPT  = (ITEMS >= 1024) ? ITEMS / 256 : 1;  // rows per thread
    constexpr int NACT = ITEMS / RPT;          // active threads in phase 1
    constexpr int NGE  = (S >= RPT) ? S / RPT : 1;  // row-groups per out-row
    constexpr int TOKBASE =
        (LEVEL == 0) ? 0 : (LEVEL == 1) ? 256 : (LEVEL == 2) ? 448
                                            : (LEVEL == 3) ? 640 : 832;
    constexpr int PER_TOK = 3 * CHK;
    constexpr int CORNER  = 2048 - 128 * S;    // pixel offset of level's grid (16-aligned)

    const int tl    = job / PER_TOK;           // token index within level
    const int rem   = job - tl * PER_TOK;
    const int ch    = rem / CHK;
    const int chunk = rem - ch * CHK;

    // Map level-local token index -> (row, col) on the 16x16 coarse grid.
    int row, col;
    if (LEVEL == 0) {
        row = tl >> 4; col = tl & 15;
    } else {
        // ring = 4 at every level >= 1
        if (tl < 64)       { row = tl >> 4;             col = tl & 15; }
        else if (tl < 128) { int k = tl - 64; row = 4 + (k >> 3);
                             int r = k & 7;             col = (r < 4) ? r : (r + 8); }
        else               { int k = tl - 128; row = 12 + (k >> 4); col = k & 15; }
    }

    const int cx  = CORNER + W * col;          // region top-left pixel (16B aligned)
    const int cy  = CORNER + W * row;
    const int oy0 = chunk * NR;                // first output row of this chunk
    const int ry0 = cy + S * oy0;              // first image row of this chunk

    const int* base = img + (size_t)ch * IMG_CH_STRIDE;
    const int tid = threadIdx.x;

    // Phase 1: every active thread owns one int4 column slice of RPT rows.
    // Fully unrolled -> RPT front-batched LDG.128 (128B in flight/thread).
    if (tid < NACT) {
        const int vcol = tid & (VC - 1);
        const int g    = tid / VC;             // row-group index
        const int4* p  = (const int4*)(base + (size_t)(ry0 + g * RPT) * IMG_DIM + cx)
                         + vcol;
        int4 a = make_int4(0, 0, 0, 0);
#pragma unroll
        for (int r = 0; r < RPT; r++) {
            int4 t = __ldcs(p);
            p += IMG_DIM / 4;
            a.x += t.x; a.y += t.y; a.z += t.z; a.w += t.w;
        }
        ((int4*)psum)[g * VC + vcol] = a;      // conflict-free 16B STS
    }
    __syncthreads();

    // Phase 2: combine NGE row-group partials x S scalar columns per output box.
    constexpr int NOUT = NR * 16;
    const int n = TOKBASE + tl;
    for (int o = tid; o < NOUT; o += 256) {
        const int oy = o >> 4;
        const int bx = o & 15;
        int sum = 0;
#pragma unroll
        for (int gg = 0; gg < NGE; gg++) {
            const int* s = psum + (oy * NGE + gg) * W + (bx << LEVEL);
#pragma unroll
            for (int i = 0; i < S; i++) sum += s[i];
        }
        // Exact floor-div by S*S (sum >= 0); value fits in [0,255].
        out[(((size_t)n * 3 + ch) << 8) + ((size_t)(oy0 + oy) << 4) + bx] =
            (float)(sum >> (2 * LEVEL));
    }
}

__global__ void __launch_bounds__(256) foveator_kernel(const int* __restrict__ img,
                                                       float* __restrict__ out) {
    __shared__ int psum[1024];                 // 256 int4 partials max (4KB)
    const int b = blockIdx.x;
    if (b < 4608)      process_level<4>(b,         img, out, psum);
    else if (b < 5760) process_level<3>(b - 4608,  img, out, psum);
    else if (b < 6336) process_level<2>(b - 5760,  img, out, psum);
    else if (b < 6912) process_level<1>(b - 6336,  img, out, psum);
    else               process_level<0>(b - 6912,  img, out, psum);
}

extern "C" void kernel_launch(void* const* d_in, const int* in_sizes, int n_in,
                              void* d_out, int out_size) {
    const int* img = (const int*)d_in[0];
    float* out = (float*)d_out;
    foveator_kernel<<<N_JOBS, 256>>>(img, out);
}

// round 15
// speedup vs baseline: 1.0683x; 1.0183x over previous
#include <cuda_runtime.h>
#include <cstdint>

// Foveated tokenizer: 5-level box-average pyramid over (3,4096,4096) int32 image.
// Token boxes exactly partition the image -> each pixel read exactly once.
// ~201 MB read + 3 MB write (float32 out), pure DRAM stream.
// R15 = R7 (proven 33.5us best) + BAND-ORDERED heavy jobs: consecutive
// blockIdx = adjacent token columns in the same 32-image-row band, same
// channel -> concurrently-resident CTAs sweep contiguous DRAM spans
// (row-buffer page hits) instead of scattered 1KB strips.

#define IMG_DIM 4096
#define IMG_CH_STRIDE (IMG_DIM * IMG_DIM)

// Job layout (heavy levels first; shapes identical to R7):
//   level 4 (s=16): 4608 jobs  [0, 4608)      - band-reordered
//   level 3 (s= 8): 1152 jobs  [4608, 5760)   - band-reordered
//   level 2 (s= 4):  576 jobs  [5760, 6336)
//   level 1 (s= 2):  576 jobs  [6336, 6912)
//   level 0 (s= 1):  768 jobs  [6912, 7680)
#define N_JOBS 7680

// Ring-layout token index from (row, col) on the 16x16 grid (levels >= 1).
__device__ __forceinline__ int ring_tl(int r, int col) {
    if (r < 4)  return r * 16 + col;
    if (r < 12) { int c8 = (col < 8) ? col : col - 8;   // col in {0..3,12..15}
                  return 64 + (r - 4) * 8 + c8; }
    return 128 + (r - 12) * 16 + col;
}

// Level 4 band order: ch -> tok-row -> chunk -> col.  Returns token-major
// job index expected by process_level<4> (= (tl*3+ch)*8 + chunk).
__device__ __forceinline__ int remap4(int b) {
    const int ch = b / 1536;
    const int j  = b - ch * 1536;
    int r, chunk, col;
    if (j < 512)       { r = j >> 7;          int j2 = j & 127;
                         chunk = j2 >> 4;     col = j2 & 15; }
    else if (j < 1024) { int t = j - 512;     r = 4 + (t >> 6);
                         int j2 = t & 63;     chunk = j2 >> 3;
                         int c8 = j2 & 7;     col = (c8 < 4) ? c8 : c8 + 8; }
    else               { int t = j - 1024;    r = 12 + (t >> 7);
                         int j2 = t & 127;    chunk = j2 >> 4; col = j2 & 15; }
    return (ring_tl(r, col) * 3 + ch) * 8 + chunk;
}

// Level 3 band order: ch -> tok-row -> chunk -> col. (= (tl*3+ch)*2 + chunk)
__device__ __forceinline__ int remap3(int b) {
    const int ch = b / 384;
    const int j  = b - ch * 384;
    int r, chunk, col;
    if (j < 128)      { r = j >> 5;          int j2 = j & 31;
                        chunk = j2 >> 4;     col = j2 & 15; }
    else if (j < 256) { int t = j - 128;     r = 4 + (t >> 4);
                        int j2 = t & 15;     chunk = j2 >> 3;
                        int c8 = j2 & 7;     col = (c8 < 4) ? c8 : c8 + 8; }
    else              { int t = j - 256;     r = 12 + (t >> 5);
                        int j2 = t & 31;     chunk = j2 >> 4; col = j2 & 15; }
    return (ring_tl(r, col) * 3 + ch) * 2 + chunk;
}

template <int LEVEL>
__device__ __forceinline__ void process_level(int job,
                                              const int* __restrict__ img,
                                              float* __restrict__ out,
                                              int* psum) {
    constexpr int S    = 1 << LEVEL;           // box stride in pixels
    constexpr int CHK  = (LEVEL == 4) ? 8 : (LEVEL == 3) ? 2 : 1; // chunks/(tok,ch)
    constexpr int NR   = 16 / CHK;             // output rows per chunk
    constexpr int W    = 16 * S;               // region width in pixels
    constexpr int VC   = W / 4;                // int4 columns
    constexpr int ROWS = NR * S;               // image rows per chunk
    constexpr int ITEMS = ROWS * VC;           // (row, vcol) load items
    constexpr int RPT  = (ITEMS >= 1024) ? ITEMS / 256 : 1;  // rows per thread
    constexpr int NACT = ITEMS / RPT;          // active threads in phase 1
    constexpr int NGE  = (S >= RPT) ? S / RPT : 1;  // row-groups per out-row
    constexpr int TOKBASE =
        (LEVEL == 0) ? 0 : (LEVEL == 1) ? 256 : (LEVEL == 2) ? 448
                                            : (LEVEL == 3) ? 640 : 832;
    constexpr int PER_TOK = 3 * CHK;
    constexpr int CORNER  = 2048 - 128 * S;    // pixel offset of level's grid (16-aligned)

    const int tl    = job / PER_TOK;           // token index within level
    const int rem   = job - tl * PER_TOK;
    const int ch    = rem / CHK;
    const int chunk = rem - ch * CHK;

    // Map level-local token index -> (row, col) on the 16x16 coarse grid.
    int row, col;
    if (LEVEL == 0) {
        row = tl >> 4; col = tl & 15;
    } else {
        // ring = 4 at every level >= 1
        if (tl < 64)       { row = tl >> 4;             col = tl & 15; }
        else if (tl < 128) { int k = tl - 64; row = 4 + (k >> 3);
                             int r = k & 7;             col = (r < 4) ? r : (r + 8); }
        else               { int k = tl - 128; row = 12 + (k >> 4); col = k & 15; }
    }

    const int cx  = CORNER + W * col;          // region top-left pixel (16B aligned)
    const int cy  = CORNER + W * row;
    const int oy0 = chunk * NR;                // first output row of this chunk
    const int ry0 = cy + S * oy0;              // first image row of this chunk

    const int* base = img + (size_t)ch * IMG_CH_STRIDE;
    const int tid = threadIdx.x;

    // Phase 1: every active thread owns one int4 column slice of RPT rows.
    // Fully unrolled -> RPT front-batched LDG.128 (128B in flight/thread).
    if (tid < NACT) {
        const int vcol = tid & (VC - 1);
        const int g    = tid / VC;             // row-group index
        const int4* p  = (const int4*)(base + (size_t)(ry0 + g * RPT) * IMG_DIM + cx)
                         + vcol;
        int4 a = make_int4(0, 0, 0, 0);
#pragma unroll
        for (int r = 0; r < RPT; r++) {
            int4 t = __ldcs(p);
            p += IMG_DIM / 4;
            a.x += t.x; a.y += t.y; a.z += t.z; a.w += t.w;
        }
        ((int4*)psum)[g * VC + vcol] = a;      // conflict-free 16B STS
    }
    __syncthreads();

    // Phase 2: combine NGE row-group partials x S scalar columns per output box.
    constexpr int NOUT = NR * 16;
    const int n = TOKBASE + tl;
    for (int o = tid; o < NOUT; o += 256) {
        const int oy = o >> 4;
        const int bx = o & 15;
        int sum = 0;
#pragma unroll
        for (int gg = 0; gg < NGE; gg++) {
            const int* s = psum + (oy * NGE + gg) * W + (bx << LEVEL);
#pragma unroll
            for (int i = 0; i < S; i++) sum += s[i];
        }
        // Exact floor-div by S*S (sum >= 0); value fits in [0,255].
        out[(((size_t)n * 3 + ch) << 8) + ((size_t)(oy0 + oy) << 4) + bx] =
            (float)(sum >> (2 * LEVEL));
    }
}

__global__ void __launch_bounds__(256) foveator_kernel(const int* __restrict__ img,
                                                       float* __restrict__ out) {
    __shared__ int psum[1024];                 // 256 int4 partials max (4KB)
    const int b = blockIdx.x;
    if (b < 4608)      process_level<4>(remap4(b),        img, out, psum);
    else if (b < 5760) process_level<3>(remap3(b - 4608), img, out, psum);
    else if (b < 6336) process_level<2>(b - 5760,         img, out, psum);
    else if (b < 6912) process_level<1>(b - 6336,         img, out, psum);
    else               process_level<0>(b - 6912,         img, out, psum);
}

extern "C" void kernel_launch(void* const* d_in, const int* in_sizes, int n_in,
                              void* d_out, int out_size) {
    const int* img = (const int*)d_in[0];
    float* out = (float*)d_out;
    foveator_kernel<<<N_JOBS, 256>>>(img, out);
}